// round 17
// baseline (speedup 1.0000x reference)
#include <cuda_runtime.h>
#include <cuda_fp16.h>
#include <cstdint>

#define Bn 128
#define Sn 256
#define Hn 1024
#define Tn 20
#define G4n 4096
#define DTn 1044
#define START_I 19
#define NBLK 128u

typedef unsigned long long u64t;

// ---------------- device scratch ----------------
__device__ float g_G[(size_t)Sn * Bn * G4n];                 // x-projection + biases (fp32)
__device__ float g_h[2][Bn * Hn];                            // fp32 h (for logits)
__device__ __align__(16) u64t g_Bf[1081344];                 // Whh+Wtag f16 B-frags, 66 kt (8.7MB)
__device__ __align__(16) uint32_t g_hAf[2][67584];           // h+onehot f16 A-frags, 66 kt (ping-pong)
__device__ __align__(16) uint4 g_xf[4194304];                // x f16 A-frags (67MB, xproj)
__device__ __align__(16) uint2 g_wf[1048576];                // W_ih f16 B-frags (8MB)
__device__ double g_loss;
__device__ unsigned g_bar_l1[16], g_bar_l2, g_bar_phase, g_lready;

// ---------------- mma wrappers ----------------
__device__ __forceinline__ void mma_f16(float* d,
    uint32_t a0, uint32_t a1, uint32_t a2, uint32_t a3,
    uint32_t b0, uint32_t b1)
{
    asm volatile(
        "mma.sync.aligned.m16n8k16.row.col.f32.f16.f16.f32 "
        "{%0,%1,%2,%3}, {%4,%5,%6,%7}, {%8,%9}, {%0,%1,%2,%3};"
        : "+f"(d[0]), "+f"(d[1]), "+f"(d[2]), "+f"(d[3])
        : "r"(a0), "r"(a1), "r"(a2), "r"(a3), "r"(b0), "r"(b1));
}
__device__ __forceinline__ uint32_t pack_f16(float x, float y) {
    __half hx = __float2half_rn(x), hy = __float2half_rn(y);
    return (uint32_t)__half_as_ushort(hx) | ((uint32_t)__half_as_ushort(hy) << 16);
}
// A-frag index of the one-hot bit pair containing `tag` for batch row r (66-kt layout)
__device__ __forceinline__ int onehot_pos(int r, int tag) {
    int kt = 64 + (tag >> 4);
    int k16 = tag & 15;
    return (r >> 4) * 8448 + kt * 128
         + ((r & 7) * 4 + ((k16 >> 1) & 3)) * 4 + ((r >> 3) & 1) + 2 * (k16 >> 3);
}

// ---------------- two-level software grid barrier ----------------
__device__ __forceinline__ void grid_bar(int bid) {
    __syncthreads();
    if (threadIdx.x == 0) {
        unsigned gen = *(volatile unsigned*)&g_bar_phase;
        __threadfence();
        unsigned t = atomicAdd(&g_bar_l1[bid >> 3], 1u);
        if (t == 7u) {
            unsigned u = atomicAdd(&g_bar_l2, 1u);
            if (u == 15u) {
#pragma unroll
                for (int i = 0; i < 16; i++) *(volatile unsigned*)&g_bar_l1[i] = 0u;
                *(volatile unsigned*)&g_bar_l2 = 0u;
                __threadfence();
                *(volatile unsigned*)&g_bar_phase = gen + 1u;
            } else {
                while (*(volatile unsigned*)&g_bar_phase == gen) {}
                __threadfence();
            }
        } else {
            while (*(volatile unsigned*)&g_bar_phase == gen) {}
            __threadfence();
        }
    }
    __syncthreads();
}

// ---------------- init ----------------
__global__ void init_kernel(const float* __restrict__ Wih, const float* __restrict__ Whh) {
    int idx = blockIdx.x * blockDim.x + threadIdx.x;   // 0 .. 4194303
    if (idx == 0) { g_loss = 0.0; g_bar_l2 = 0u; g_bar_phase = 0u; g_lready = 0u; }
    if (idx < 16) g_bar_l1[idx] = 0u;
    // A-frag one-hot region preset: zero, with START(=19) bit set for every row, both parities
    if (idx < 4096) {
        int par = idx >> 11;
        int u = idx & 2047;
        int mt = u >> 8;
        int w = u & 255;
        int ktq = w >> 7;
        int lpos = w & 127;
        // START: kt=65 (ktq=1), k16=3 -> pairq=1, half8=0, elem=1 -> hi half = 1.0
        uint32_t val = 0u;
        if (ktq == 1 && ((lpos >> 2) & 3) == 1 && ((lpos >> 1) & 1) == 0)
            val = pack_f16(0.f, 1.f);
        g_hAf[par][mt * 8448 + (64 + ktq) * 128 + lpos] = val;
    }
    if (idx < 1081344) {   // B-frags: kt<64 from Whh, kt 64-65 from Wtag columns of Wih
        int lane = idx & 31;
        int r2 = idx >> 5;
        int kt = r2 % 66;
        int r3 = r2 / 66;
        int nt = r3 & 3;
        int bid = r3 >> 2;
        int g = lane >> 2, tig = lane & 3;
        int n = nt * 1024 + bid * 8 + g;
        uint32_t r0, r1;
        if (kt < 64) {
            const float* W = Whh + (size_t)n * Hn + kt * 16 + 2 * tig;
            r0 = pack_f16(W[0], W[1]);
            r1 = pack_f16(W[8], W[9]);
        } else {
            int t0 = (kt - 64) * 16 + 2 * tig;
            const float* W = Wih + (size_t)n * DTn + Hn;
            float v0 = (t0 < Tn) ? W[t0] : 0.f;
            float v1 = (t0 + 1 < Tn) ? W[t0 + 1] : 0.f;
            float v8 = (t0 + 8 < Tn) ? W[t0 + 8] : 0.f;
            float v9 = (t0 + 9 < Tn) ? W[t0 + 9] : 0.f;
            r0 = pack_f16(v0, v1);
            r1 = pack_f16(v8, v9);
        }
        g_Bf[((size_t)(bid * 4 + nt) * 66 + kt) * 32 + lane] = (u64t)r0 | ((u64t)r1 << 32);
    }
    if (idx < 1048576) {   // W_ih f16 B-frags (xproj)
        int lane = idx & 31;
        int kt   = (idx >> 5) & 63;
        int nt2  = idx >> 11;
        int g = lane >> 2, tig = lane & 3;
        int n = nt2 * 8 + g;
        int k0 = kt * 16 + 2 * tig;
        const float* W = Wih + (size_t)n * DTn;
        g_wf[idx] = make_uint2(pack_f16(W[k0], W[k0 + 1]), pack_f16(W[k0 + 8], W[k0 + 9]));
    }
}

// ---------------- x -> f16 A-frags (one-time) ----------------
__global__ void xprep_kernel(const float* __restrict__ x) {
    int idx = blockIdx.x * blockDim.x + threadIdx.x;
    int lane = idx & 31;
    int kt = (idx >> 5) & 63;
    int mt = idx >> 11;
    int g = lane >> 2, tig = lane & 3;
    int m0 = mt * 16 + g;
    int m1 = m0 + 8;
    int k0 = kt * 16 + 2 * tig;
    const float* r0 = x + ((size_t)((m0 & 127) * 256 + (m0 >> 7))) * Hn;
    const float* r1 = x + ((size_t)((m1 & 127) * 256 + (m1 >> 7))) * Hn;
    float2 v00 = *(const float2*)(r0 + k0);
    float2 v01 = *(const float2*)(r0 + k0 + 8);
    float2 v10 = *(const float2*)(r1 + k0);
    float2 v11 = *(const float2*)(r1 + k0 + 8);
    g_xf[idx] = make_uint4(pack_f16(v00.x, v00.y), pack_f16(v10.x, v10.y),
                           pack_f16(v01.x, v01.y), pack_f16(v11.x, v11.y));
}

// ---------------- phase 1: x-projection via single-pass f16 HMMA (R16, unchanged) ----------------
__global__ __launch_bounds__(256) void xproj_kernel(
    const float* __restrict__ bih, const float* __restrict__ bhh)
{
    const int tid = threadIdx.x;
    const int wid = tid >> 5, lane = tid & 31;
    const int g = lane >> 2, tig = lane & 3;
    const int wm = wid & 1, wn = wid >> 1;
    const int mt0 = blockIdx.y * 8 + wm * 4;
    const int nt0 = blockIdx.x * 16 + wn * 4;

    const uint4* Af = g_xf + (size_t)mt0 * 2048 + lane;
    const uint2* Bf = g_wf + (size_t)nt0 * 2048 + lane;

    float dacc[4][4][4];
#pragma unroll
    for (int i = 0; i < 4; i++)
#pragma unroll
        for (int j = 0; j < 4; j++)
#pragma unroll
            for (int e = 0; e < 4; e++) dacc[i][j][e] = 0.f;

    uint4 a[4]; uint2 b[4];
#pragma unroll
    for (int i = 0; i < 4; i++) a[i] = __ldg(Af + i * 2048);
#pragma unroll
    for (int j = 0; j < 4; j++) b[j] = __ldg(Bf + j * 2048);

    for (int kt = 0; kt < 64; kt++) {
        uint4 an[4]; uint2 bn[4];
        if (kt < 63) {
#pragma unroll
            for (int i = 0; i < 4; i++) an[i] = __ldg(Af + i * 2048 + (kt + 1) * 32);
#pragma unroll
            for (int j = 0; j < 4; j++) bn[j] = __ldg(Bf + j * 2048 + (kt + 1) * 32);
        }
#pragma unroll
        for (int i = 0; i < 4; i++)
#pragma unroll
            for (int j = 0; j < 4; j++)
                mma_f16(dacc[i][j], a[i].x, a[i].y, a[i].z, a[i].w, b[j].x, b[j].y);
#pragma unroll
        for (int i = 0; i < 4; i++) a[i] = an[i];
#pragma unroll
        for (int j = 0; j < 4; j++) b[j] = bn[j];
    }

#pragma unroll
    for (int j = 0; j < 4; j++) {
        int n = (nt0 + j) * 8 + 2 * tig;
        float b0 = bih[n] + bhh[n];
        float b1 = bih[n + 1] + bhh[n + 1];
#pragma unroll
        for (int i = 0; i < 4; i++) {
            int m = (mt0 + i) * 16 + g;
            *(float2*)(g_G + (size_t)m * G4n + n) =
                make_float2(dacc[i][j][0] + b0, dacc[i][j][1] + b1);
            *(float2*)(g_G + (size_t)(m + 8) * G4n + n) =
                make_float2(dacc[i][j][2] + b0, dacc[i][j][3] + b1);
        }
    }
}

// ---------------- persistent loop: one-hot-in-GEMM, wk0 = GEMM+epilogue, wk1 = logits ----------------
// smem: [0..1024) red, [1024..68608) Bf frags (66 kt)
#define LOOP_SMEM 68608

__global__ __launch_bounds__(512, 1) void loop_kernel(
    const float* __restrict__ Wout, const float* __restrict__ bout,
    const int* __restrict__ tags, const int* __restrict__ mask,
    float* __restrict__ out)
{
    extern __shared__ __align__(16) unsigned char smem[];
    float* red = (float*)smem;
    const uint2* Bh = (const uint2*)(smem + 1024);

    const int bid = blockIdx.x;
    const int tid = threadIdx.x;
    const int wid = tid >> 5;
    const int lane = tid & 31;
    const int g = lane >> 2, tig = lane & 3;
    const int wk = wid >> 3;
    const int wm = wid & 7;
    const int gtid = tid & 255;

    {
        const uint4* src = (const uint4*)g_Bf + (size_t)bid * 4224;
        uint4* dst = (uint4*)(smem + 1024);
        for (int u = tid; u < 4224; u += 512) dst[u] = src[u];
    }
    __syncthreads();

    const int b1 = wm * 16 + g;
    const int b2 = b1 + 8;
    const int kkg0 = bid * 8 + 2 * tig;

    float creg[2][2] = {{0.f, 0.f}, {0.f, 0.f}};
    double lossAcc = 0.0;
    int ptg[2] = {START_I, START_I};   // per-parity last one-hot tag (writer thread only)

    // logits for step ls (h(ls) in g_h[(ls+1)&1]); wk1 threads only.
    auto do_logits = [&](int ls, bool feed) {
        const float4* h4 = (const float4*)(g_h[(ls + 1) & 1] + bid * Hn);
        float4 hvv = __ldcg(h4 + gtid);
        const float4* W4 = (const float4*)Wout;
        float p[Tn];
#pragma unroll
        for (int t = 0; t < Tn; t++) {
            float4 w = __ldg(W4 + t * 256 + gtid);
            p[t] = hvv.x * w.x + hvv.y * w.y + hvv.z * w.z + hvv.w * w.w;
        }
#pragma unroll
        for (int t = 0; t < Tn; t++) {
#pragma unroll
            for (int o = 16; o > 0; o >>= 1)
                p[t] += __shfl_xor_sync(0xffffffffu, p[t], o);
        }
        if (lane == 0) {
#pragma unroll
            for (int t = 0; t < Tn; t++) red[(gtid >> 5) * Tn + t] = p[t];
        }
        asm volatile("bar.sync 1, 256;" ::: "memory");
        if (gtid < 32) {
            float l = -3.402823466e38f;
            if (gtid < Tn) {
                l = bout[gtid];
#pragma unroll
                for (int w = 0; w < 8; w++) l += red[w * Tn + gtid];
            }
            float v = l; int idx = gtid;
#pragma unroll
            for (int o = 16; o > 0; o >>= 1) {
                float v2 = __shfl_xor_sync(0xffffffffu, v, o);
                int   i2 = __shfl_xor_sync(0xffffffffu, idx, o);
                if (v2 > v || (v2 == v && i2 < idx)) { v = v2; idx = i2; }
            }
            if (mask[bid * Sn + ls] != 0) {
                float e = (gtid < Tn) ? expf(l - v) : 0.f;
#pragma unroll
                for (int o = 16; o > 0; o >>= 1)
                    e += __shfl_xor_sync(0xffffffffu, e, o);
                int y = tags[bid * Sn + ls];
                float ly = __shfl_sync(0xffffffffu, l, y);
                if (gtid == 0) lossAcc += (double)(v + logf(e) - ly);
            }
            if (feed && gtid == 0) {
                // write one-hot(argmax) for batch=bid into parity used by step ls+1
                int par = (ls + 1) & 1;
                int pOld = onehot_pos(bid, ptg[par]);
                int pNew = onehot_pos(bid, idx);
                g_hAf[par][pOld] = 0u;
                g_hAf[par][pNew] = (idx & 1) ? pack_f16(0.f, 1.f) : pack_f16(1.f, 0.f);
                ptg[par] = idx;
                __threadfence();
                atomicAdd(&g_lready, 1u);
            }
        }
    };

    for (int s = 0; s < Sn; s++) {
        float2 Gv[2][4];
        if (tid < 256) {
#pragma unroll
            for (int r2 = 0; r2 < 2; r2++) {
                int r = r2 ? b2 : b1;
                const float* Gp = g_G + (size_t)(s * Bn + r) * G4n + kkg0;
#pragma unroll
                for (int nt = 0; nt < 4; nt++)
                    Gv[r2][nt] = __ldcs((const float2*)(Gp + nt * 1024));
            }
        }

        float dacc[4][4];
#pragma unroll
        for (int nt = 0; nt < 4; nt++)
#pragma unroll
            for (int e = 0; e < 4; e++) dacc[nt][e] = 0.f;

        const int par = s & 1;
        if (wk == 1) {
            if (s > 0) do_logits(s - 1, true);   // publishes one-hot + counter
        } else {
            const uint4* Af4 = (const uint4*)g_hAf[par] + (wm * 2112 + lane);
            if (s > 0) {
                // main h GEMM, kt 0..63
                uint4 afs[3];
#pragma unroll
                for (int d = 0; d < 3; d++) afs[d] = __ldcg(Af4 + d * 32);
#pragma unroll
                for (int kt = 0; kt < 64; kt++) {
                    const int sl = kt % 3;
                    uint4 af = afs[sl];
                    if (kt + 3 < 64) afs[sl] = __ldcg(Af4 + (kt + 3) * 32);
                    uint2 b0 = Bh[(0 * 66 + kt) * 32 + lane];
                    uint2 b1r = Bh[(1 * 66 + kt) * 32 + lane];
                    uint2 b2r = Bh[(2 * 66 + kt) * 32 + lane];
                    uint2 b3 = Bh[(3 * 66 + kt) * 32 + lane];
                    mma_f16(dacc[0], af.x, af.y, af.z, af.w, b0.x, b0.y);
                    mma_f16(dacc[1], af.x, af.y, af.z, af.w, b1r.x, b1r.y);
                    mma_f16(dacc[2], af.x, af.y, af.z, af.w, b2r.x, b2r.y);
                    mma_f16(dacc[3], af.x, af.y, af.z, af.w, b3.x, b3.y);
                }
                // wait for all blocks' one-hot writes (normally already done)
                if (tid == 0) {
                    while (*(volatile unsigned*)&g_lready < (unsigned)s * 128u) {}
                    __threadfence();
                }
                asm volatile("bar.sync 2, 256;" ::: "memory");
            }
            // one-hot k-tiles 64,65 (step 0: START preset by init)
#pragma unroll
            for (int q = 0; q < 2; q++) {
                uint4 af = __ldcg(Af4 + (64 + q) * 32);
                uint2 b0 = Bh[(0 * 66 + 64 + q) * 32 + lane];
                uint2 b1r = Bh[(1 * 66 + 64 + q) * 32 + lane];
                uint2 b2r = Bh[(2 * 66 + 64 + q) * 32 + lane];
                uint2 b3 = Bh[(3 * 66 + 64 + q) * 32 + lane];
                mma_f16(dacc[0], af.x, af.y, af.z, af.w, b0.x, b0.y);
                mma_f16(dacc[1], af.x, af.y, af.z, af.w, b1r.x, b1r.y);
                mma_f16(dacc[2], af.x, af.y, af.z, af.w, b2r.x, b2r.y);
                mma_f16(dacc[3], af.x, af.y, af.z, af.w, b3.x, b3.y);
            }
        }

        // ---- epilogue (threads 0-255 = wk0) ----
        const int po = par ^ 1;
        if (tid < 256) {
#pragma unroll
            for (int r2 = 0; r2 < 2; r2++) {
                int r = r2 ? b2 : b1;
                float h01[2];
#pragma unroll
                for (int e = 0; e < 2; e++) {
                    int de = r2 * 2 + e;
                    float G0 = e ? Gv[r2][0].y : Gv[r2][0].x;
                    float G1 = e ? Gv[r2][1].y : Gv[r2][1].x;
                    float G2 = e ? Gv[r2][2].y : Gv[r2][2].x;
                    float G3 = e ? Gv[r2][3].y : Gv[r2][3].x;
                    float gi = dacc[0][de] + G0;
                    float gf = dacc[1][de] + G1;
                    float gg = dacc[2][de] + G2;
                    float go = dacc[3][de] + G3;
                    gi = 1.f / (1.f + __expf(-gi));
                    gf = 1.f / (1.f + __expf(-gf));
                    gg = tanhf(gg);
                    go = 1.f / (1.f + __expf(-go));
                    creg[r2][e] = gf * creg[r2][e] + gi * gg;
                    h01[e] = go * tanhf(creg[r2][e]);
                }
                *(float2*)(g_h[po] + r * Hn + kkg0) = make_float2(h01[0], h01[1]);
                int idx = ((r >> 4) * 8448) + ((bid >> 1) * 128)
                        + (((r & 7) * 4 + tig) * 4) + ((r >> 3) & 1) + 2 * (bid & 1);
                g_hAf[po][idx] = pack_f16(h01[0], h01[1]);
            }
        }
        grid_bar(bid);
    }

    // tail: logits(255) (loss only)
    if (wk == 1) do_logits(Sn - 1, false);
    if (tid == 256) atomicAdd(&g_loss, lossAcc);
    grid_bar(bid);
    if (bid == 0 && tid == 0) out[0] = (float)(*(volatile double*)&g_loss);
}

// ---------------- launch ----------------
extern "C" void kernel_launch(void* const* d_in, const int* in_sizes, int n_in,
                              void* d_out, int out_size)
{
    const float *x = nullptr, *Wih = nullptr, *Whh = nullptr;
    const float *bih = nullptr, *bhh = nullptr, *Wout = nullptr, *bout = nullptr;
    const int *tags = nullptr, *maskp = nullptr;
    for (int i = 0; i < n_in; i++) {
        int sz = in_sizes[i];
        const void* p = d_in[i];
        switch (sz) {
            case 33554432: x = (const float*)p; break;
            case 4276224:  Wih = (const float*)p; break;
            case 4194304:  Whh = (const float*)p; break;
            case 4096:     if (!bih) bih = (const float*)p; else bhh = (const float*)p; break;
            case 32768:    if (!tags) tags = (const int*)p; else maskp = (const int*)p; break;
            case 20480:    Wout = (const float*)p; break;
            case 20:       bout = (const float*)p; break;
            default: break;
        }
    }

    cudaFuncSetAttribute(loop_kernel, cudaFuncAttributeMaxDynamicSharedMemorySize, LOOP_SMEM);

    init_kernel<<<16384, 256>>>(Wih, Whh);                               // #1
    xprep_kernel<<<16384, 256>>>(x);                                     // #2
    xproj_kernel<<<dim3(32, 256), 256>>>(bih, bhh);                      // #3
    loop_kernel<<<NBLK, 512, LOOP_SMEM>>>(Wout, bout, tags, maskp, (float*)d_out);  // #4 (profiled)
}